// round 4
// baseline (speedup 1.0000x reference)
#include <cuda_runtime.h>
#include <math.h>
#include <stdint.h>

#define BB   32
#define LL   1024
#define CH   34
#define DD   256
#define EE   8
#define PP   4
#define PRED 96
#define RR   128
#define NBLK 128      // <= 148 SMs: all blocks resident at occupancy 1 -> barrier is safe
#define NTHR 512

// smem layout (float offsets)
#define WSTR     260
#define WS_OFF   0                       // 64 x 260 expert-W tile; phase C reuses as sf[1024]
#define AS_OFF   (64 * WSTR)             // 32 x 260 xp tile
#define MISC     (AS_OFF + 32 * WSTR)
#define SXC_OFF  (MISC)                  // 512 (8 batches x 64 raw-normed samples)
#define RED_OFF  (MISC + 512)            // 64
#define MB_OFF   (MISC + 576)            // 8  (means)
#define RS_OFF   (MISC + 584)            // 8  (rstds)
#define SLOG_OFF (MISC + 592)            // 256 logits
#define SG_OFF   (MISC + 848)            // 256 gates
#define SMEM_FLOATS (MISC + 1120)
#define SMEM_BYTES  (SMEM_FLOATS * 4)    // ~104.5 KB -> 1 block/SM (fine)

__device__ float g_s1[NBLK];             // per (batch, quarter) sums
__device__ float g_s2[NBLK];
__device__ float g_xcraw[BB * 64];       // raw first 64 samples per batch
__device__ float g_gates[RR * EE];
__device__ float g_part[EE * RR * DD];   // 1 MB gated partials
__device__ unsigned g_barcnt[2];
__device__ float g_dummy[4];

__device__ __forceinline__ void cp16(void* dst_smem, const void* src_gmem) {
    uint32_t d = (uint32_t)__cvta_generic_to_shared(dst_smem);
    asm volatile("cp.async.cg.shared.global [%0], [%1], 16;" :: "r"(d), "l"(src_gmem));
}
__device__ __forceinline__ float ldcg(const float* p) {
    float v; asm volatile("ld.global.cg.f32 %0, [%1];" : "=f"(v) : "l"(p)); return v;
}

// Monotonic release/acquire grid barrier (no gpu-scope membar -> no L1 flush).
// Counter is a multiple of NBLK at every launch start (graph-replay safe).
__device__ __forceinline__ void grid_barrier(int k) {
    __syncthreads();
    if (threadIdx.x == 0) {
        unsigned old;
        asm volatile("atom.release.gpu.global.add.u32 %0, [%1], 1;"
                     : "=r"(old) : "l"(&g_barcnt[k]) : "memory");
        unsigned target = old - (old % NBLK) + NBLK;
        unsigned cur;
        do {
            __nanosleep(64);
            asm volatile("ld.acquire.gpu.global.u32 %0, [%1];"
                         : "=r"(cur) : "l"(&g_barcnt[k]) : "memory");
        } while (cur < target);
    }
    __syncthreads();
}

__global__ void __launch_bounds__(NTHR, 1)
fused_kernel(const float* __restrict__ x,
             const float* __restrict__ W_proj,
             const float* __restrict__ b_proj,
             const float* __restrict__ W_router,
             const float* __restrict__ b_router,
             const float* __restrict__ W_experts,
             const float* __restrict__ b_experts,
             const float* __restrict__ W_head,
             const float* __restrict__ b_head,
             float* __restrict__ out) {
    extern __shared__ float sm[];
    const int bid = blockIdx.x;
    const int tid = threadIdx.x;

    // GEMM tile coords: 8 experts x 4 h-tiles(64) x 4 r-tiles(32 rows = 8 batches)
    const int e2  = bid >> 4;
    const int hb2 = (bid >> 2) & 3;
    const int rb  = bid & 3;

    // ---- stage expert W tile (64 x 256) via cp.async; completes during phase A
    {
        const float* Wb = W_experts + ((size_t)e2 * DD + hb2 * 64) * DD;
#pragma unroll
        for (int i = 0; i < 8; i++) {
            int q = tid + NTHR * i;
            int row = q >> 6, c4 = q & 63;
            cp16(sm + WS_OFF + row * WSTR + c4 * 4, Wb + row * DD + c4 * 4);
        }
        asm volatile("cp.async.commit_group;");
    }

    // ================= Phase A: coalesced stats + weight prefetch ============
    {
        int b = bid >> 2, seg = bid & 3;                 // 4 segments of 256 positions
        const float* xrow = x + (size_t)b * (LL * CH);
        int base = seg * 8704;                            // 256*34 floats per segment
        float s1 = 0.f, s2 = 0.f;
#pragma unroll
        for (int i = 0; i < 5; i++) {
            int v4 = tid + NTHR * i;                      // float4 idx (2176 per segment)
            if (v4 < 2176) {
                float4 q = __ldg((const float4*)(xrow + base) + v4);
                int w0 = base + v4 * 4;
                int m = w0 % 34;
                int jm = 2 - m; if (jm < 0) jm += 34;     // component hitting channel 2
                if (jm < 4) {
                    float val = (jm == 0) ? q.x : (jm == 1) ? q.y : (jm == 2) ? q.z : q.w;
                    s1 += val; s2 += val * val;
                    int l = (w0 + jm) / 34;
                    if (l < 64) g_xcraw[b * 64 + l] = val;   // only seg 0 hits
                }
            }
        }

        // spread weight prefetch (warms L2 during the gather + barrier)
        float pf = 0.f;
        if (tid < 192) {
            float4 wq = __ldg((const float4*)W_head + bid * 192 + tid);
            pf += wq.x + wq.y + wq.z + wq.w;
        }
        if (bid < 8)        pf += __ldg(W_proj + bid * 512 + tid);
        else if (bid < 12)  pf += __ldg(W_router + (bid - 8) * 512 + tid);
        else if (bid < 16)  pf += __ldg(b_experts + (bid - 12) * 512 + tid);
        else if (bid == 16) {
            if (tid < 256)  pf += __ldg(b_proj + tid);
            if (tid < PRED) pf += __ldg(b_head + tid);
            if (tid < EE)   pf += __ldg(b_router + tid);
        }
        if (pf == 1.2345e-30f) g_dummy[0] = pf;

#pragma unroll
        for (int off = 16; off > 0; off >>= 1) {
            s1 += __shfl_xor_sync(0xffffffffu, s1, off);
            s2 += __shfl_xor_sync(0xffffffffu, s2, off);
        }
        if ((tid & 31) == 0) { sm[RED_OFF + (tid >> 5)] = s1; sm[RED_OFF + 16 + (tid >> 5)] = s2; }
        __syncthreads();
        if (tid == 0) {
            float a = 0.f, c = 0.f;
#pragma unroll
            for (int w = 0; w < 16; w++) { a += sm[RED_OFF + w]; c += sm[RED_OFF + 16 + w]; }
            g_s1[b * 4 + seg] = a;
            g_s2[b * 4 + seg] = c;
        }
    }
    grid_barrier(0);

    // ================= Phase B: stats/xp/gates (local) + expert GEMM =========
    {
        const int bat0 = rb * 8;                  // tile spans batches bat0..bat0+7

        // gather partial sums for my 8 batches (4 segs each)
        if (tid < 32)      sm[RED_OFF + tid] = ldcg(g_s1 + bat0 * 4 + tid);
        else if (tid < 64) sm[RED_OFF + tid] = ldcg(g_s2 + bat0 * 4 + (tid - 32));
        __syncthreads();
        if (tid < 8) {
            float s1 = sm[RED_OFF + tid * 4] + sm[RED_OFF + tid * 4 + 1]
                     + sm[RED_OFF + tid * 4 + 2] + sm[RED_OFF + tid * 4 + 3];
            float s2 = sm[RED_OFF + 32 + tid * 4] + sm[RED_OFF + 32 + tid * 4 + 1]
                     + sm[RED_OFF + 32 + tid * 4 + 2] + sm[RED_OFF + 32 + tid * 4 + 3];
            float mu = s1 * (1.0f / 1024.0f);
            float var = s2 * (1.0f / 1024.0f) - mu * mu;
            sm[MB_OFF + tid] = mu;
            sm[RS_OFF + tid] = rsqrtf(var + 1e-5f);
        }
        __syncthreads();

        // xc: 8 batches x 64 samples, one per thread
        {
            int bl = tid >> 6, l = tid & 63;
            sm[SXC_OFF + tid] = (ldcg(g_xcraw + (bat0 + bl) * 64 + l) - sm[MB_OFF + bl]) * sm[RS_OFF + bl];
        }
        __syncthreads();

        // xp tile: 32 rows x 256, thread = (dd, row-half)
        {
            int dd = tid & 255, rh = tid >> 8;
            const float4* wrow = (const float4*)(W_proj + dd * 16);
            float4 w0 = wrow[0], w1 = wrow[1], w2 = wrow[2], w3 = wrow[3];
            float bp = __ldg(b_proj + dd);
#pragma unroll
            for (int r = rh * 16; r < rh * 16 + 16; r++) {
                const float* xc = sm + SXC_OFF + (r >> 2) * 64 + (r & 3) * 16;
                float acc = bp;
                acc += w0.x * xc[0]  + w0.y * xc[1]  + w0.z * xc[2]  + w0.w * xc[3];
                acc += w1.x * xc[4]  + w1.y * xc[5]  + w1.z * xc[6]  + w1.w * xc[7];
                acc += w2.x * xc[8]  + w2.y * xc[9]  + w2.z * xc[10] + w2.w * xc[11];
                acc += w3.x * xc[12] + w3.y * xc[13] + w3.z * xc[14] + w3.w * xc[15];
                sm[AS_OFF + r * WSTR + dd] = acc;
            }
        }
        __syncthreads();

        // router logits: thread = (row, expert, k-half)
        {
            int r = tid >> 4, e = (tid >> 1) & 7, half = tid & 1;
            const float* wr = W_router + e * DD + half * 128;
            const float* ap = sm + AS_OFF + r * WSTR + half * 128;
            float acc = 0.f;
#pragma unroll
            for (int k = 0; k < 128; k += 4) {
                float4 w = *(const float4*)(wr + k);
                acc += w.x * ap[k] + w.y * ap[k + 1] + w.z * ap[k + 2] + w.w * ap[k + 3];
            }
            acc += __shfl_xor_sync(0xffffffffu, acc, 1);
            if (half == 0) sm[SLOG_OFF + r * 8 + e] = acc + __ldg(b_router + e);
        }
        __syncthreads();
        if (tid < 32) {
            int r = tid;
            float lg[EE], m = -1e30f;
#pragma unroll
            for (int e = 0; e < EE; e++) { lg[e] = sm[SLOG_OFF + r * 8 + e]; m = fmaxf(m, lg[e]); }
            float sum = 0.f;
#pragma unroll
            for (int e = 0; e < EE; e++) { lg[e] = __expf(lg[e] - m); sum += lg[e]; }
            float inv = 1.0f / sum;
#pragma unroll
            for (int e = 0; e < EE; e++) {
                float g = lg[e] * inv;
                sm[SG_OFF + r * 8 + e] = g;
                g_gates[(rb * 32 + r) * EE + e] = g;   // redundant same-value writes OK
            }
        }

        asm volatile("cp.async.wait_group 0;" ::: "memory");
        __syncthreads();

        // GEMM 32r x 64c: warp tile 8r x 16c, lane tile 2x2
        {
            int w = tid >> 5, l = tid & 31;
            int r0 = (w & 3) * 8 + (l & 3) * 2;
            int c0 = (w >> 2) * 16 + (l >> 2) * 2;
            float acc00 = 0.f, acc01 = 0.f, acc10 = 0.f, acc11 = 0.f;
            const float* ap0 = sm + AS_OFF + r0 * WSTR;
            const float* ap1 = ap0 + WSTR;
            const float* wp0 = sm + WS_OFF + c0 * WSTR;
            const float* wp1 = wp0 + WSTR;
#pragma unroll 4
            for (int kk = 0; kk < DD; kk += 4) {
                float4 a0 = *(const float4*)(ap0 + kk);
                float4 a1 = *(const float4*)(ap1 + kk);
                float4 b0 = *(const float4*)(wp0 + kk);
                float4 b1 = *(const float4*)(wp1 + kk);
                acc00 += a0.x * b0.x + a0.y * b0.y + a0.z * b0.z + a0.w * b0.w;
                acc01 += a0.x * b1.x + a0.y * b1.y + a0.z * b1.z + a0.w * b1.w;
                acc10 += a1.x * b0.x + a1.y * b0.y + a1.z * b0.z + a1.w * b0.w;
                acc11 += a1.x * b1.x + a1.y * b1.y + a1.z * b1.z + a1.w * b1.w;
            }
            float g0 = sm[SG_OFF + r0 * 8 + e2];
            float g1 = sm[SG_OFF + (r0 + 1) * 8 + e2];
            float* dst = g_part + ((size_t)e2 * RR + rb * 32 + r0) * DD + hb2 * 64;
            dst[c0]          = g0 * acc00;
            dst[c0 + 1]      = g0 * acc01;
            dst[DD + c0]     = g1 * acc10;
            dst[DD + c0 + 1] = g1 * acc11;
        }
    }
    grid_barrier(1);

    // ================= Phase C: reduce experts + rescale + head GEMV =========
    {
        int b = bid >> 2, jt = bid & 3;

        if (tid == 0) {
            float s1 = 0.f, s2 = 0.f;
#pragma unroll
            for (int s = 0; s < 4; s++) { s1 += ldcg(g_s1 + b * 4 + s); s2 += ldcg(g_s2 + b * 4 + s); }
            float mean = s1 * (1.0f / 1024.0f);
            float var  = s2 * (1.0f / 1024.0f) - mean * mean;
            sm[MB_OFF] = mean;
            sm[RS_OFF] = sqrtf(var + 1e-5f);     // stdev
        }
        if (tid >= 32 && tid < 64)
            sm[SG_OFF + tid - 32] = ldcg(g_gates + b * 32 + (tid - 32));  // 4 patches x 8
        __syncthreads();
        float mean  = sm[MB_OFF];
        float stdev = sm[RS_OFF];

        // combined + gated bias + rescale -> sf (reuses Ws region)
#pragma unroll
        for (int i = 0; i < 2; i++) {
            int l = tid + NTHR * i;
            int p = l >> 8, h = l & 255;
            int r = b * PP + p;
            float v = 0.f;
#pragma unroll
            for (int e = 0; e < EE; e++) {
                v += ldcg(g_part + ((size_t)e * RR + r) * DD + h);
                v += sm[SG_OFF + p * 8 + e] * __ldg(b_experts + e * DD + h);
            }
            sm[WS_OFF + l] = v * stdev + mean;
        }
        __syncthreads();

        // head GEMV: 24 rows x 16 lanes
        if (tid < 384) {
            int row = tid >> 4, s = tid & 15;
            int j = jt * 24 + row;
            const float4* wr = (const float4*)(W_head + (size_t)j * LL) + s * 16;
            const float4* sv = (const float4*)(sm + WS_OFF) + s * 16;
            float a = 0.f;
#pragma unroll
            for (int i = 0; i < 16; i++) {
                float4 w = __ldg(wr + i);
                float4 xv = sv[i];
                a += w.x * xv.x + w.y * xv.y + w.z * xv.z + w.w * xv.w;
            }
#pragma unroll
            for (int off = 8; off > 0; off >>= 1)
                a += __shfl_down_sync(0xffffffffu, a, off, 16);
            if (s == 0) out[b * PRED + j] = a + __ldg(b_head + j);
        }
    }
}

extern "C" void kernel_launch(void* const* d_in, const int* in_sizes, int n_in,
                              void* d_out, int out_size) {
    const float* x         = (const float*)d_in[0];
    const float* W_proj    = (const float*)d_in[4];
    const float* b_proj    = (const float*)d_in[5];
    const float* W_router  = (const float*)d_in[6];
    const float* b_router  = (const float*)d_in[7];
    const float* W_experts = (const float*)d_in[8];
    const float* b_experts = (const float*)d_in[9];
    const float* W_head    = (const float*)d_in[10];
    const float* b_head    = (const float*)d_in[11];
    float* out = (float*)d_out;

    cudaFuncSetAttribute(fused_kernel,
                         cudaFuncAttributeMaxDynamicSharedMemorySize, SMEM_BYTES);
    fused_kernel<<<NBLK, NTHR, SMEM_BYTES>>>(x, W_proj, b_proj, W_router, b_router,
                                             W_experts, b_experts, W_head, b_head, out);
}

// round 5
// speedup vs baseline: 1.2193x; 1.2193x over previous
#include <cuda_runtime.h>
#include <math.h>
#include <stdint.h>

#define BB   32
#define LL   1024
#define CH   34
#define DD   256
#define EE   8
#define PP   4
#define PRED 96
#define NBLK 128      // <= 148 SMs: all blocks resident at occupancy 1 -> barrier safe
#define NTHR 512

typedef unsigned long long ull;

// packed f32x2 fused multiply-add (halves FFMA instruction count)
#define FMA2(d, a, b, c) \
    asm("fma.rn.f32x2 %0, %1, %2, %3;" : "=l"(d) : "l"(a), "l"(b), "l"(c))
__device__ __forceinline__ float f2lo(ull v) { return __uint_as_float((unsigned)v); }
__device__ __forceinline__ float f2hi(ull v) { return __uint_as_float((unsigned)(v >> 32)); }

// smem layout (float offsets)
#define WSTR   260
#define WS_OFF 0                         // 64 x 260 expert-W tile; C reuses as sf[1024]
#define AS_OFF 16640                     // 32 x 260 raw-u tile; C reuses rows 0..3 as xp
#define SXR    24960                     // 512 raw x samples (8 batches x 64)
#define SW1    25472                     // 256 w1[d]
#define SBP    25728                     // 256 b_proj
#define RED    25984                     // 64 reduce scratch
#define STAT   26048                     // mu, sd, rsd
#define SLOG   26056                     // 32 logits
#define SG     26088                     // 32 gates
#define CPART  (AS_OFF + 4 * WSTR)       // C router partials (256), inside free As rows
#define SMEM_FLOATS 26120
#define SMEM_BYTES  (SMEM_FLOATS * 4)    // ~102 KB -> 1 block/SM

// g_part layout: [e][row][h], row 0..127 = raw U rows, 128 = c1_e, 129 = c2_e
#define GPIDX(e, r, h) ((((e) * 130) + (r)) * 256 + (h))

__device__ float g_s1[NBLK];
__device__ float g_s2[NBLK];
__device__ float g_part[EE * 130 * DD];
__device__ unsigned g_barcnt[1];
__device__ float g_dummy[4];

__device__ __forceinline__ void cp16(void* dst_smem, const void* src_gmem) {
    uint32_t d = (uint32_t)__cvta_generic_to_shared(dst_smem);
    asm volatile("cp.async.cg.shared.global [%0], [%1], 16;" :: "r"(d), "l"(src_gmem));
}
__device__ __forceinline__ float ldcg(const float* p) {
    float v; asm volatile("ld.global.cg.f32 %0, [%1];" : "=f"(v) : "l"(p)); return v;
}

// Monotonic release/acquire grid barrier (no gpu-scope membar -> no L1 flush).
__device__ __forceinline__ void grid_barrier() {
    __syncthreads();
    if (threadIdx.x == 0) {
        unsigned old;
        asm volatile("atom.release.gpu.global.add.u32 %0, [%1], 1;"
                     : "=r"(old) : "l"(&g_barcnt[0]) : "memory");
        unsigned target = old - (old % NBLK) + NBLK;
        unsigned cur;
        do {
            __nanosleep(64);
            asm volatile("ld.acquire.gpu.global.u32 %0, [%1];"
                         : "=r"(cur) : "l"(&g_barcnt[0]) : "memory");
        } while (cur < target);
    }
    __syncthreads();
}

__global__ void __launch_bounds__(NTHR, 1)
fused_kernel(const float* __restrict__ x,
             const float* __restrict__ W_proj,
             const float* __restrict__ b_proj,
             const float* __restrict__ W_router,
             const float* __restrict__ b_router,
             const float* __restrict__ W_experts,
             const float* __restrict__ b_experts,
             const float* __restrict__ W_head,
             const float* __restrict__ b_head,
             float* __restrict__ out) {
    extern __shared__ float sm[];
    const int bid = blockIdx.x;
    const int tid = threadIdx.x;

    // GEMM tile coords: 8 experts x 4 h-tiles(64) x 4 r-tiles(32 rows = 8 batches)
    const int e2  = bid >> 4;
    const int hb2 = (bid >> 2) & 3;
    const int rb  = bid & 3;
    const int bat0 = rb * 8;

    // ---- (1) stage expert W tile (64 x 256) via cp.async
    {
        const float* Wb = W_experts + ((size_t)e2 * DD + hb2 * 64) * DD;
#pragma unroll
        for (int i = 0; i < 8; i++) {
            int q = tid + NTHR * i;
            int row = q >> 6, c4 = q & 63;
            cp16(sm + WS_OFF + row * WSTR + c4 * 4, Wb + row * DD + c4 * 4);
        }
        asm volatile("cp.async.commit_group;");
    }

    // ---- (2) raw x samples for this tile's 8 batches (first 64 positions each)
    {
        int bl = tid >> 6, l = tid & 63;
        sm[SXR + tid] = __ldg(x + ((size_t)(bat0 + bl) * LL + l) * CH + 2);
    }

    // ---- (3) stats partials (coalesced full scan of (b,seg)) + weight prefetch
    {
        int b = bid >> 2, seg = bid & 3;
        const float* xrow = x + (size_t)b * (LL * CH);
        int base = seg * 8704;
        float s1 = 0.f, s2 = 0.f;
#pragma unroll
        for (int i = 0; i < 5; i++) {
            int v4 = tid + NTHR * i;
            if (v4 < 2176) {
                float4 q = __ldg((const float4*)(xrow + base) + v4);
                int w0 = base + v4 * 4;
                int m = w0 % 34;
                int jm = 2 - m; if (jm < 0) jm += 34;
                if (jm < 4) {
                    float val = (jm == 0) ? q.x : (jm == 1) ? q.y : (jm == 2) ? q.z : q.w;
                    s1 += val; s2 += val * val;
                }
            }
        }

        float pf = 0.f;
        if (tid < 192) {
            float4 wq = __ldg((const float4*)W_head + bid * 192 + tid);
            pf += wq.x + wq.y + wq.z + wq.w;
        }
        if (bid < 4)       pf += __ldg(W_router + bid * 512 + tid);
        else if (bid < 8)  pf += __ldg(b_experts + (bid - 4) * 512 + tid);
        else if (bid == 8) { if (tid < PRED) pf += __ldg(b_head + tid);
                             if (tid < EE)   pf += __ldg(b_router + tid); }
        if (pf == 1.2345e-30f) g_dummy[0] = pf;

#pragma unroll
        for (int off = 16; off > 0; off >>= 1) {
            s1 += __shfl_xor_sync(0xffffffffu, s1, off);
            s2 += __shfl_xor_sync(0xffffffffu, s2, off);
        }
        if ((tid & 31) == 0) { sm[RED + (tid >> 5)] = s1; sm[RED + 16 + (tid >> 5)] = s2; }
        __syncthreads();   // also covers SXR staging
        if (tid == 0) {
            float a = 0.f, c = 0.f;
#pragma unroll
            for (int w = 0; w < 16; w++) { a += sm[RED + w]; c += sm[RED + 16 + w]; }
            g_s1[bid] = a;
            g_s2[bid] = c;
        }
    }

    // ---- (4) raw projection u-tile: As[r][d] = sum_k W_proj[d][k]*xraw[r][k]
    {
        int d = tid & 255, half = tid >> 8;
        const ulonglong2* wp = (const ulonglong2*)(W_proj + d * 16);
        ulonglong2 w0 = wp[0], w1v = wp[1], w2 = wp[2], w3 = wp[3];

        if (half == 0) {
            ull ones = 0x3F8000003F800000ull, s = 0ull;
            FMA2(s, w0.x, ones, s); FMA2(s, w0.y, ones, s);
            FMA2(s, w1v.x, ones, s); FMA2(s, w1v.y, ones, s);
            FMA2(s, w2.x, ones, s); FMA2(s, w2.y, ones, s);
            FMA2(s, w3.x, ones, s); FMA2(s, w3.y, ones, s);
            sm[SW1 + d] = f2lo(s) + f2hi(s);
            sm[SBP + d] = __ldg(b_proj + d);
        }
#pragma unroll
        for (int r = half * 16; r < half * 16 + 16; r++) {
            const ulonglong2* x2 = (const ulonglong2*)(sm + SXR + (r >> 2) * 64 + (r & 3) * 16);
            ulonglong2 xa = x2[0], xb = x2[1], xc = x2[2], xd = x2[3];
            ull acc = 0ull;
            FMA2(acc, w0.x, xa.x, acc); FMA2(acc, w0.y, xa.y, acc);
            FMA2(acc, w1v.x, xb.x, acc); FMA2(acc, w1v.y, xb.y, acc);
            FMA2(acc, w2.x, xc.x, acc); FMA2(acc, w2.y, xc.y, acc);
            FMA2(acc, w3.x, xd.x, acc); FMA2(acc, w3.y, xd.y, acc);
            sm[AS_OFF + r * WSTR + d] = f2lo(acc) + f2hi(acc);
        }
    }
    asm volatile("cp.async.wait_group 0;" ::: "memory");
    __syncthreads();

    // ---- (5) raw GEMM: U[r][c] = sum_d As[r][d] * Ws[c][d]  (ungated!)
    {
        int w = tid >> 5, l = tid & 31;
        int r0 = (w & 3) * 8 + (l & 3) * 2;
        int c0 = (w >> 2) * 16 + (l >> 2) * 2;
        ull a00 = 0ull, a01 = 0ull, a10 = 0ull, a11 = 0ull;
        const ulonglong2* ap0 = (const ulonglong2*)(sm + AS_OFF + r0 * WSTR);
        const ulonglong2* ap1 = (const ulonglong2*)(sm + AS_OFF + (r0 + 1) * WSTR);
        const ulonglong2* bp0 = (const ulonglong2*)(sm + WS_OFF + c0 * WSTR);
        const ulonglong2* bp1 = (const ulonglong2*)(sm + WS_OFF + (c0 + 1) * WSTR);
#pragma unroll 8
        for (int k = 0; k < 64; k++) {
            ulonglong2 a0 = ap0[k], a1 = ap1[k];
            ulonglong2 b0 = bp0[k], b1 = bp1[k];
            FMA2(a00, a0.x, b0.x, a00); FMA2(a00, a0.y, b0.y, a00);
            FMA2(a01, a0.x, b1.x, a01); FMA2(a01, a0.y, b1.y, a01);
            FMA2(a10, a1.x, b0.x, a10); FMA2(a10, a1.y, b0.y, a10);
            FMA2(a11, a1.x, b1.x, a11); FMA2(a11, a1.y, b1.y, a11);
        }
        int rg = rb * 32 + r0;
        int hg = hb2 * 64 + c0;
        g_part[GPIDX(e2, rg, hg)]         = f2lo(a00) + f2hi(a00);
        g_part[GPIDX(e2, rg, hg + 1)]     = f2lo(a01) + f2hi(a01);
        g_part[GPIDX(e2, rg + 1, hg)]     = f2lo(a10) + f2hi(a10);
        g_part[GPIDX(e2, rg + 1, hg + 1)] = f2lo(a11) + f2hi(a11);
    }

    // ---- (6) epilogue (rb==0 blocks only): c1_e[h] = w1.W_e,  c2_e[h] = b_proj.W_e
    if (rb == 0 && tid < 128) {
        int kind = tid >> 6, c = tid & 63;
        const ulonglong2* v2 = (const ulonglong2*)(sm + (kind ? SBP : SW1));
        const ulonglong2* wp = (const ulonglong2*)(sm + WS_OFF + c * WSTR);
        ull acc = 0ull;
#pragma unroll 8
        for (int k = 0; k < 64; k++) {
            ulonglong2 v = v2[k], wv = wp[k];
            FMA2(acc, v.x, wv.x, acc);
            FMA2(acc, v.y, wv.y, acc);
        }
        g_part[GPIDX(e2, 128 + kind, hb2 * 64 + c)] = f2lo(acc) + f2hi(acc);
    }

    grid_barrier();

    // ================= Phase C: gates + finalize + head GEMV =================
    {
        int b = bid >> 2, jt = bid & 3;

        if (tid == 0) {
            float s1 = 0.f, s2 = 0.f;
#pragma unroll
            for (int s = 0; s < 4; s++) { s1 += ldcg(g_s1 + b * 4 + s); s2 += ldcg(g_s2 + b * 4 + s); }
            float mu = s1 * (1.0f / 1024.0f);
            float var = s2 * (1.0f / 1024.0f) - mu * mu;
            float sd = sqrtf(var + 1e-5f);
            sm[STAT] = mu; sm[STAT + 1] = sd; sm[STAT + 2] = 1.0f / sd;
        }
        if (tid >= 64 && tid < 128)
            sm[SXR + tid - 64] = __ldg(x + ((size_t)b * LL + (tid - 64)) * CH + 2);
        __syncthreads();

        float mu = sm[STAT], sd = sm[STAT + 1], rsd = sm[STAT + 2];

        // xp rows 0..3 (for router only): xp = (u - mu*w1)*rsd + b_proj
        {
            int d = tid & 255, pg = tid >> 8;
            const ulonglong2* wp = (const ulonglong2*)(W_proj + d * 16);
            ulonglong2 w0 = wp[0], w1v = wp[1], w2 = wp[2], w3 = wp[3];
            ull ones = 0x3F8000003F800000ull, s = 0ull;
            FMA2(s, w0.x, ones, s); FMA2(s, w0.y, ones, s);
            FMA2(s, w1v.x, ones, s); FMA2(s, w1v.y, ones, s);
            FMA2(s, w2.x, ones, s); FMA2(s, w2.y, ones, s);
            FMA2(s, w3.x, ones, s); FMA2(s, w3.y, ones, s);
            float w1d = f2lo(s) + f2hi(s);
            float bpd = __ldg(b_proj + d);
#pragma unroll
            for (int i = 0; i < 2; i++) {
                int p = pg * 2 + i;
                const ulonglong2* x2 = (const ulonglong2*)(sm + SXR + p * 16);
                ulonglong2 xa = x2[0], xb = x2[1], xc = x2[2], xd = x2[3];
                ull acc = 0ull;
                FMA2(acc, w0.x, xa.x, acc); FMA2(acc, w0.y, xa.y, acc);
                FMA2(acc, w1v.x, xb.x, acc); FMA2(acc, w1v.y, xb.y, acc);
                FMA2(acc, w2.x, xc.x, acc); FMA2(acc, w2.y, xc.y, acc);
                FMA2(acc, w3.x, xd.x, acc); FMA2(acc, w3.y, xd.y, acc);
                float u = f2lo(acc) + f2hi(acc);
                sm[AS_OFF + p * WSTR + d] = (u - mu * w1d) * rsd + bpd;
            }
        }
        __syncthreads();

        // router logits
        if (tid < 256) {
            int pe = tid >> 3, sl = tid & 7;
            int p = pe >> 3, e = pe & 7;
            const float* wr = W_router + e * DD + sl * 32;
            const float* ap = sm + AS_OFF + p * WSTR + sl * 32;
            float acc = 0.f;
#pragma unroll
            for (int k = 0; k < 32; k += 4) {
                float4 wv = *(const float4*)(wr + k);
                acc += wv.x * ap[k] + wv.y * ap[k + 1] + wv.z * ap[k + 2] + wv.w * ap[k + 3];
            }
            sm[CPART + pe * 8 + sl] = acc;
        }
        __syncthreads();
        if (tid < 32) {
            float acc = __ldg(b_router + (tid & 7));
#pragma unroll
            for (int s = 0; s < 8; s++) acc += sm[CPART + tid * 8 + s];
            sm[SLOG + tid] = acc;
        }
        __syncthreads();
        if (tid < PP) {
            int p = tid;
            float m = -1e30f;
#pragma unroll
            for (int e = 0; e < EE; e++) m = fmaxf(m, sm[SLOG + p * 8 + e]);
            float ex[EE], sum = 0.f;
#pragma unroll
            for (int e = 0; e < EE; e++) { ex[e] = __expf(sm[SLOG + p * 8 + e] - m); sum += ex[e]; }
            float inv = 1.0f / sum;
#pragma unroll
            for (int e = 0; e < EE; e++) sm[SG + p * 8 + e] = ex[e] * inv;
        }
        __syncthreads();

        // finalize: flat[l] = sum_e g*U - mu*sum_e g*c1 + sd*sum_e g*(c2+b_e) + mu
        {
            int h = tid & 255, pg = tid >> 8;
            float c1v[EE], c2v[EE];
#pragma unroll
            for (int e = 0; e < EE; e++) {
                c1v[e] = ldcg(g_part + GPIDX(e, 128, h));
                c2v[e] = ldcg(g_part + GPIDX(e, 129, h)) + __ldg(b_experts + e * DD + h);
            }
#pragma unroll
            for (int i = 0; i < 2; i++) {
                int p = pg * 2 + i;
                int r = b * PP + p;
                float A = 0.f, Bc = 0.f, Cc = 0.f;
#pragma unroll
                for (int e = 0; e < EE; e++) {
                    float g = sm[SG + p * 8 + e];
                    A  += g * ldcg(g_part + GPIDX(e, r, h));
                    Bc += g * c1v[e];
                    Cc += g * c2v[e];
                }
                sm[WS_OFF + p * 256 + h] = A - mu * Bc + sd * Cc + mu;
            }
        }
        __syncthreads();

        // head GEMV: 24 rows x 16 lanes
        if (tid < 384) {
            int row = tid >> 4, s = tid & 15;
            int j = jt * 24 + row;
            const float4* wr = (const float4*)(W_head + (size_t)j * LL) + s * 16;
            const float4* sv = (const float4*)(sm + WS_OFF) + s * 16;
            float a = 0.f;
#pragma unroll
            for (int i = 0; i < 16; i++) {
                float4 wv = __ldg(wr + i);
                float4 xv = sv[i];
                a += wv.x * xv.x + wv.y * xv.y + wv.z * xv.z + wv.w * xv.w;
            }
#pragma unroll
            for (int off = 8; off > 0; off >>= 1)
                a += __shfl_down_sync(0xffffffffu, a, off, 16);
            if (s == 0) out[b * PRED + j] = a + __ldg(b_head + j);
        }
    }
}

extern "C" void kernel_launch(void* const* d_in, const int* in_sizes, int n_in,
                              void* d_out, int out_size) {
    const float* x         = (const float*)d_in[0];
    const float* W_proj    = (const float*)d_in[4];
    const float* b_proj    = (const float*)d_in[5];
    const float* W_router  = (const float*)d_in[6];
    const float* b_router  = (const float*)d_in[7];
    const float* W_experts = (const float*)d_in[8];
    const float* b_experts = (const float*)d_in[9];
    const float* W_head    = (const float*)d_in[10];
    const float* b_head    = (const float*)d_in[11];
    float* out = (float*)d_out;

    cudaFuncSetAttribute(fused_kernel,
                         cudaFuncAttributeMaxDynamicSharedMemorySize, SMEM_BYTES);
    fused_kernel<<<NBLK, NTHR, SMEM_BYTES>>>(x, W_proj, b_proj, W_router, b_router,
                                             W_experts, b_experts, W_head, b_head, out);
}

// round 6
// speedup vs baseline: 1.6977x; 1.3924x over previous
#include <cuda_runtime.h>
#include <math.h>
#include <stdint.h>

#define BB   32
#define LL   1024
#define CH   34
#define DD   256
#define EE   8
#define PP   4
#define PRED 96
#define NBLK 128      // <= 148 SMs: all blocks wave-1 resident -> grid barrier safe
#define NTHR 512

// shared memory layout (float offsets), static 48KB budget
#define WPT  0                    // wp_t[17][256]: W_proj^T, row16 = b_proj
#define WES  4352                 // We_s[16][260]: expert-W slice (padded stride)
#define SXC  8512                 // 64 normalized patch samples (post) / unused (pre)
#define RED  8576                 // 32 reduce scratch
#define STAT 8608                 // mu, sd, rsd
#define SLOG 8612                 // 32 logits
#define SG   8644                 // 32 gates
#define SF   8676                 // 1024 flat row
#define SM_FLOATS 9700

__device__ float g_M[EE * 17 * DD];   // M_e[k][h], k=16 row = b_proj . We^T
__device__ float g_R[17 * EE];        // R[k][e],   k=16 row = b_proj.Wr^T + br
__device__ float g_s1[NBLK];
__device__ float g_s2[NBLK];
__device__ unsigned g_barcnt[1];
__device__ float g_dummy[4];

__device__ __forceinline__ void cp16(void* dst_smem, const void* src_gmem) {
    uint32_t d = (uint32_t)__cvta_generic_to_shared(dst_smem);
    asm volatile("cp.async.cg.shared.global [%0], [%1], 16;" :: "r"(d), "l"(src_gmem));
}
__device__ __forceinline__ float ldcg(const float* p) {
    float v; asm volatile("ld.global.cg.f32 %0, [%1];" : "=f"(v) : "l"(p)); return v;
}

// Monotonic release/acquire grid barrier (no gpu-scope membar -> no L1 flush).
__device__ __forceinline__ void grid_barrier() {
    __syncthreads();
    if (threadIdx.x == 0) {
        unsigned old;
        asm volatile("atom.release.gpu.global.add.u32 %0, [%1], 1;"
                     : "=r"(old) : "l"(&g_barcnt[0]) : "memory");
        unsigned target = old - (old % NBLK) + NBLK;
        unsigned cur;
        do {
            __nanosleep(64);
            asm volatile("ld.acquire.gpu.global.u32 %0, [%1];"
                         : "=r"(cur) : "l"(&g_barcnt[0]) : "memory");
        } while (cur < target);
    }
    __syncthreads();
}

__global__ void __launch_bounds__(NTHR, 1)
fused_kernel(const float* __restrict__ x,
             const float* __restrict__ W_proj,
             const float* __restrict__ b_proj,
             const float* __restrict__ W_router,
             const float* __restrict__ b_router,
             const float* __restrict__ W_experts,
             const float* __restrict__ b_experts,
             const float* __restrict__ W_head,
             const float* __restrict__ b_head,
             float* __restrict__ out) {
    __shared__ float sm[SM_FLOATS];
    const int bid = blockIdx.x;
    const int tid = threadIdx.x;

    // M-construction tile coords: 8 experts x 16 col-tiles of 16
    const int e2 = bid >> 4;
    const int ct = bid & 15;

    // ---- (1) stage We slice (16 rows x 256) via cp.async
    {
        const float* Wb = W_experts + ((size_t)e2 * DD + ct * 16) * DD;
#pragma unroll
        for (int i = 0; i < 2; i++) {
            int q = tid + NTHR * i;               // 1024 float4s
            int row = q >> 6, c4 = q & 63;
            cp16(sm + WES + row * 260 + c4 * 4, Wb + row * DD + c4 * 4);
        }
        asm volatile("cp.async.commit_group;");
    }

    // ---- (2) Wp transpose into smem: wp_t[k][d]; row 16 = b_proj
    {
#pragma unroll
        for (int i = 0; i < 2; i++) {
            int idx = tid + NTHR * i;             // 1024 float4s of W_proj
            int d = idx >> 2, kq = idx & 3;
            float4 v = __ldg((const float4*)W_proj + idx);
            sm[WPT + (kq * 4 + 0) * 256 + d] = v.x;
            sm[WPT + (kq * 4 + 1) * 256 + d] = v.y;
            sm[WPT + (kq * 4 + 2) * 256 + d] = v.z;
            sm[WPT + (kq * 4 + 3) * 256 + d] = v.w;
        }
        if (tid < 256) sm[WPT + 16 * 256 + tid] = __ldg(b_proj + tid);
    }

    // ---- (3) stats partials (coalesced scan) + W_head L2 prefetch
    {
        int b = bid >> 2, seg = bid & 3;
        const float* xrow = x + (size_t)b * (LL * CH);
        int base = seg * 8704;
        float s1 = 0.f, s2 = 0.f;
#pragma unroll
        for (int i = 0; i < 5; i++) {
            int v4 = tid + NTHR * i;
            if (v4 < 2176) {
                float4 q = __ldg((const float4*)(xrow + base) + v4);
                int w0 = base + v4 * 4;
                int m = w0 % 34;
                int jm = 2 - m; if (jm < 0) jm += 34;
                if (jm < 4) {
                    float val = (jm == 0) ? q.x : (jm == 1) ? q.y : (jm == 2) ? q.z : q.w;
                    s1 += val; s2 += val * val;
                }
            }
        }

        float pf = 0.f;
        if (tid < 192) {                           // full W_head coverage -> L2
            float4 wq = __ldg((const float4*)W_head + bid * 192 + tid);
            pf += wq.x + wq.y + wq.z + wq.w;
        }
        if (bid == 0) {
            if (tid < PRED) pf += __ldg(b_head + tid);
            if (tid < EE)   pf += __ldg(b_router + tid);
        }
        if (pf == 1.2345e-30f) g_dummy[0] = pf;

#pragma unroll
        for (int off = 16; off > 0; off >>= 1) {
            s1 += __shfl_xor_sync(0xffffffffu, s1, off);
            s2 += __shfl_xor_sync(0xffffffffu, s2, off);
        }
        if ((tid & 31) == 0) { sm[RED + (tid >> 5)] = s1; sm[RED + 16 + (tid >> 5)] = s2; }
    }

    asm volatile("cp.async.wait_group 0;" ::: "memory");
    __syncthreads();

    if (tid == 0) {
        float a = 0.f, c = 0.f;
#pragma unroll
        for (int w = 0; w < 16; w++) { a += sm[RED + w]; c += sm[RED + 16 + w]; }
        g_s1[bid] = a;
        g_s2[bid] = c;
    }

    // ---- (4) M_e construction: M[k][c] = sum_d wp_t[k][d] * We_s[c][d]
    if (tid < 272) {
        int k = tid >> 4, c = tid & 15;
        const float4* wp4 = (const float4*)(sm + WPT + k * 256);
        const float4* we4 = (const float4*)(sm + WES + c * 260);
        float a0 = 0.f, a1 = 0.f, a2 = 0.f, a3 = 0.f;
#pragma unroll 8
        for (int i = 0; i < 64; i++) {
            float4 wv = wp4[i], ev = we4[i];
            a0 += wv.x * ev.x; a1 += wv.y * ev.y;
            a2 += wv.z * ev.z; a3 += wv.w * ev.w;
        }
        g_M[(e2 * 17 + k) * DD + ct * 16 + c] = (a0 + a1) + (a2 + a3);
    }

    // ---- (5) folded router R[k][e2] (ct==0 blocks; threads 272..288)
    if (ct == 0 && tid >= 272 && tid < 289) {
        int k = tid - 272;
        const float* wp = sm + WPT + k * 256;
        const float* wr = W_router + e2 * DD;
        float a0 = 0.f, a1 = 0.f, a2 = 0.f, a3 = 0.f;
#pragma unroll 8
        for (int d = 0; d < DD; d += 4) {
            a0 += wp[d]     * __ldg(wr + d);
            a1 += wp[d + 1] * __ldg(wr + d + 1);
            a2 += wp[d + 2] * __ldg(wr + d + 2);
            a3 += wp[d + 3] * __ldg(wr + d + 3);
        }
        float acc = (a0 + a1) + (a2 + a3);
        if (k == 16) acc += __ldg(b_router + e2);
        g_R[k * EE + e2] = acc;
    }

    grid_barrier();

    // ================= Post: per-batch gates + comb + head GEMV ==============
    {
        int b = bid >> 2, jt = bid & 3;

        // raw samples (issue early; latency overlaps stats finalize)
        float rawv = 0.f;
        if (tid < 64) rawv = __ldg(x + ((size_t)b * LL + tid) * CH + 2);

        if (tid == 0) {
            float s1 = 0.f, s2 = 0.f;
#pragma unroll
            for (int s = 0; s < 4; s++) { s1 += ldcg(g_s1 + b * 4 + s); s2 += ldcg(g_s2 + b * 4 + s); }
            float mu = s1 * (1.0f / 1024.0f);
            float var = s2 * (1.0f / 1024.0f) - mu * mu;
            float sd = sqrtf(var + 1e-5f);
            sm[STAT] = mu; sm[STAT + 1] = sd; sm[STAT + 2] = 1.0f / sd;
        }
        __syncthreads();
        float mu = sm[STAT], sd = sm[STAT + 1], rsd = sm[STAT + 2];
        if (tid < 64) sm[SXC + tid] = (rawv - mu) * rsd;
        __syncthreads();

        // folded router logits: 32 threads, p = tid>>3, e = tid&7
        if (tid < 32) {
            int p = tid >> 3, e = tid & 7;
            float acc = ldcg(g_R + 16 * EE + e);
            const float* xc = sm + SXC + p * 16;
#pragma unroll
            for (int k = 0; k < 16; k++) acc += xc[k] * ldcg(g_R + k * EE + e);
            sm[SLOG + tid] = acc;
        }
        __syncthreads();
        if (tid < PP) {
            int p = tid;
            float m = -1e30f;
#pragma unroll
            for (int e = 0; e < EE; e++) m = fmaxf(m, sm[SLOG + p * 8 + e]);
            float ex[EE], sum = 0.f;
#pragma unroll
            for (int e = 0; e < EE; e++) { ex[e] = __expf(sm[SLOG + p * 8 + e] - m); sum += ex[e]; }
            float inv = 1.0f / sum;
#pragma unroll
            for (int e = 0; e < EE; e++) sm[SG + p * 8 + e] = ex[e] * inv;
        }
        __syncthreads();

        // comb: thread h handles all 4 patches
        if (tid < 256) {
            int h = tid;
            float acc0 = 0.f, acc1 = 0.f, acc2 = 0.f, acc3 = 0.f;
#pragma unroll
            for (int e = 0; e < EE; e++) {
                float m[17];
#pragma unroll
                for (int k = 0; k < 17; k++) m[k] = ldcg(g_M + (e * 17 + k) * DD + h);
                float cb = m[16] + __ldg(b_experts + e * DD + h);
                float g0 = sm[SG + 0 * 8 + e], g1 = sm[SG + 1 * 8 + e];
                float g2 = sm[SG + 2 * 8 + e], g3 = sm[SG + 3 * 8 + e];
                float s0 = cb, s1 = cb, s2 = cb, s3 = cb;
#pragma unroll
                for (int k = 0; k < 16; k++) {
                    float mk = m[k];
                    s0 += sm[SXC +       k] * mk;
                    s1 += sm[SXC + 16  + k] * mk;
                    s2 += sm[SXC + 32  + k] * mk;
                    s3 += sm[SXC + 48  + k] * mk;
                }
                acc0 += g0 * s0; acc1 += g1 * s1; acc2 += g2 * s2; acc3 += g3 * s3;
            }
            sm[SF +       h] = acc0 * sd + mu;
            sm[SF + 256 + h] = acc1 * sd + mu;
            sm[SF + 512 + h] = acc2 * sd + mu;
            sm[SF + 768 + h] = acc3 * sd + mu;
        }
        __syncthreads();

        // head GEMV: 24 rows x 16 lanes
        if (tid < 384) {
            int row = tid >> 4, s = tid & 15;
            int j = jt * 24 + row;
            const float4* wr = (const float4*)(W_head + (size_t)j * LL) + s * 16;
            const float4* sv = (const float4*)(sm + SF) + s * 16;
            float a = 0.f;
#pragma unroll
            for (int i = 0; i < 16; i++) {
                float4 wv = __ldg(wr + i);
                float4 xv = sv[i];
                a += wv.x * xv.x + wv.y * xv.y + wv.z * xv.z + wv.w * xv.w;
            }
#pragma unroll
            for (int off = 8; off > 0; off >>= 1)
                a += __shfl_down_sync(0xffffffffu, a, off, 16);
            if (s == 0) out[b * PRED + j] = a + __ldg(b_head + j);
        }
    }
}

extern "C" void kernel_launch(void* const* d_in, const int* in_sizes, int n_in,
                              void* d_out, int out_size) {
    const float* x         = (const float*)d_in[0];
    const float* W_proj    = (const float*)d_in[4];
    const float* b_proj    = (const float*)d_in[5];
    const float* W_router  = (const float*)d_in[6];
    const float* b_router  = (const float*)d_in[7];
    const float* W_experts = (const float*)d_in[8];
    const float* b_experts = (const float*)d_in[9];
    const float* W_head    = (const float*)d_in[10];
    const float* b_head    = (const float*)d_in[11];
    float* out = (float*)d_out;

    fused_kernel<<<NBLK, NTHR>>>(x, W_proj, b_proj, W_router, b_router,
                                 W_experts, b_experts, W_head, b_head, out);
}